// round 8
// baseline (speedup 1.0000x reference)
#include <cuda_runtime.h>
#include <math_constants.h>
#include <math.h>
#include <cstdint>

#define TOKENS 16384
#define HIDDEN 7168
#define NEXP   256
#define TOPK   8
#define BK     16
#define NCH    (HIDDEN / BK)   // 448
#define TAU    1e-4f

// SMEM per stage: A [16][128] f32 = 8KB | B [16][256] f32 = 16KB
#define ST_BYTES 24576
#define OFF_A    0
#define OFF_B    8192
#define SMEM_TOTAL (2 * ST_BYTES)

__device__ float g_logits[(size_t)TOKENS * NEXP];
__device__ float g_Bt[(size_t)NEXP * HIDDEN];    // chunk-blocked [ch][k][n]
__device__ int   g_nflag;
__device__ int   g_flagged[TOKENS];

#define CPA16(dst, src) \
    asm volatile("cp.async.cg.shared.global [%0], [%1], 16;" \
                 :: "r"(dst), "l"(src) : "memory")

#define LDS128F(v, addr) \
    asm volatile("ld.shared.v4.f32 {%0,%1,%2,%3}, [%4];" \
                 : "=f"((v).x), "=f"((v).y), "=f"((v).z), "=f"((v).w) : "r"(addr))

// ---------------------------------------------------------------------------
// Kernel 0: transpose W [n][k] -> g_Bt [chunk][k][n] (SMEM-image layout).
// ---------------------------------------------------------------------------
__global__ __launch_bounds__(256)
void convert_b_kernel(const float* __restrict__ W) {
    if (blockIdx.x == 0 && threadIdx.x == 0) g_nflag = 0;   // per-launch reset

    const int ch = blockIdx.x;
    const int n  = threadIdx.x;
    const float* src = W + (size_t)n * HIDDEN + ch * BK;
    float* dst = g_Bt + (size_t)ch * (BK * NEXP);
    #pragma unroll
    for (int j = 0; j < 4; j++) {
        float4 v = *(const float4*)(src + 4 * j);
        dst[(4 * j + 0) * NEXP + n] = v.x;
        dst[(4 * j + 1) * NEXP + n] = v.y;
        dst[(4 * j + 2) * NEXP + n] = v.z;
        dst[(4 * j + 3) * NEXP + n] = v.w;
    }
}

// ---------------------------------------------------------------------------
// Kernel 1: fp32 FFMA SGEMM tuned for issue efficiency.
// CTA = 128 tokens x 256 experts (grid 128, single wave), 256 threads,
// per-thread tile 8M x 16N -> 128 FFMA per 6 LDS.128 per k (95.5% mix).
// ---------------------------------------------------------------------------
__global__ __launch_bounds__(256, 1)
void gemm_ffma(const float* __restrict__ A)
{
    extern __shared__ char smem[];
    uint32_t sb;
    asm("{ .reg .u64 t; cvta.to.shared.u64 t, %1; cvt.u32.u64 %0, t; }"
        : "=r"(sb) : "l"((void*)smem));

    const int tid = threadIdx.x;
    const int tx  = tid & 15;           // N: cols tx*8 and tx*8+128
    const int ty  = tid >> 4;           // M: rows ty*8..
    const int bm  = blockIdx.x * 128;

    // A loader: 2 threads/row, 8 consecutive k each
    const int arow  = tid >> 1;
    const int apart = tid & 1;
    const float* Agp = A + (size_t)(bm + arow) * HIDDEN + apart * 8;

    // B loader: thread t copies 64B: k-plane t>>4, n-seg (t&15)*16
    const int bk = tid >> 4;
    const int bn = (tid & 15) * 16;

    float cc[8][16];
    #pragma unroll
    for (int i = 0; i < 8; i++)
        #pragma unroll
        for (int j = 0; j < 16; j++) cc[i][j] = 0.0f;

#define LOAD_B_ASYNC(nc, st) do {                                              \
        const float* __s = g_Bt + (size_t)(nc) * (BK * NEXP) + bk * NEXP + bn; \
        uint32_t __d = sb + (st) * ST_BYTES + OFF_B + bk * 1024 + bn * 4;      \
        CPA16(__d,      __s);                                                  \
        CPA16(__d + 16, __s + 4);                                              \
        CPA16(__d + 32, __s + 8);                                              \
        CPA16(__d + 48, __s + 12);                                             \
        asm volatile("cp.async.commit_group;" ::: "memory");                   \
    } while (0)

#define LOAD_A_LDG(nc, av) do {                                                \
        float4 t0 = __ldg((const float4*)(Agp + (size_t)(nc) * BK));           \
        float4 t1 = __ldg((const float4*)(Agp + (size_t)(nc) * BK + 4));       \
        (av)[0] = t0.x; (av)[1] = t0.y; (av)[2] = t0.z; (av)[3] = t0.w;        \
        (av)[4] = t1.x; (av)[5] = t1.y; (av)[6] = t1.z; (av)[7] = t1.w;        \
    } while (0)

#define STORE_A(st, av) do {                                                   \
        const uint32_t __ab = sb + (st) * ST_BYTES + OFF_A + arow * 4;         \
        _Pragma("unroll")                                                      \
        for (int j = 0; j < 8; j++)                                            \
            asm volatile("st.shared.f32 [%0], %1;"                             \
                         :: "r"(__ab + (apart * 8 + j) * 512), "f"((av)[j])    \
                         : "memory");                                          \
    } while (0)

    // ---- prologue: stage 0 ----
    {
        LOAD_B_ASYNC(0, 0);
        float av[8];
        LOAD_A_LDG(0, av);
        STORE_A(0, av);
        asm volatile("cp.async.wait_group 0;" ::: "memory");
        __syncthreads();
    }

    // ---- main loop over 448 chunks of K=16 ----
    for (int c = 0; c < NCH; c++) {
        const int s   = c & 1;
        const bool np = (c + 1 < NCH);
        float av[8];
        if (np) {
            LOAD_B_ASYNC(c + 1, s ^ 1);
            LOAD_A_LDG(c + 1, av);
        }

        const uint32_t abase = sb + s * ST_BYTES + OFF_A + ty * 32;
        const uint32_t bbase = sb + s * ST_BYTES + OFF_B + tx * 32;

        #pragma unroll 4
        for (int k = 0; k < BK; k++) {
            float4 a0, a1, b0, b1, b2, b3;
            LDS128F(a0, abase + k * 512);
            LDS128F(a1, abase + k * 512 + 16);
            LDS128F(b0, bbase + k * 1024);
            LDS128F(b1, bbase + k * 1024 + 16);
            LDS128F(b2, bbase + k * 1024 + 512);
            LDS128F(b3, bbase + k * 1024 + 528);
            float ar[8] = {a0.x, a0.y, a0.z, a0.w, a1.x, a1.y, a1.z, a1.w};
            float br[16] = {b0.x, b0.y, b0.z, b0.w, b1.x, b1.y, b1.z, b1.w,
                            b2.x, b2.y, b2.z, b2.w, b3.x, b3.y, b3.z, b3.w};
            #pragma unroll
            for (int i = 0; i < 8; i++)
                #pragma unroll
                for (int j = 0; j < 16; j++)
                    cc[i][j] += ar[i] * br[j];
        }

        if (np) {
            STORE_A(s ^ 1, av);
            asm volatile("cp.async.wait_group 0;" ::: "memory");
        }
        __syncthreads();
    }

    // ---- epilogue: 8 rows x (8 cols @ tx*8, 8 cols @ tx*8+128) ----
    #pragma unroll
    for (int i = 0; i < 8; i++) {
        float* out = g_logits + (size_t)(bm + ty * 8 + i) * NEXP;
        *(float4*)(out + tx * 8)       = make_float4(cc[i][0], cc[i][1], cc[i][2], cc[i][3]);
        *(float4*)(out + tx * 8 + 4)   = make_float4(cc[i][4], cc[i][5], cc[i][6], cc[i][7]);
        *(float4*)(out + tx * 8 + 128) = make_float4(cc[i][8], cc[i][9], cc[i][10], cc[i][11]);
        *(float4*)(out + tx * 8 + 132) = make_float4(cc[i][12], cc[i][13], cc[i][14], cc[i][15]);
    }
}

// ---------------------------------------------------------------------------
// route_one: reference-exact routing for one token (validated R4-R7).
// ---------------------------------------------------------------------------
__device__ __forceinline__ void route_one(const float* __restrict__ row,
                                          const float* __restrict__ bias,
                                          float* __restrict__ out,
                                          int write_idx, int token, int lane,
                                          int do_flag)
{
    const unsigned FULL = 0xffffffffu;

    float4 l0 = *(const float4*)(row + lane * 8);
    float4 l1 = *(const float4*)(row + lane * 8 + 4);
    float4 b0 = *(const float4*)(bias + lane * 8);
    float4 b1 = *(const float4*)(bias + lane * 8 + 4);

    float lv[8] = {l0.x, l0.y, l0.z, l0.w, l1.x, l1.y, l1.z, l1.w};
    float bb[8] = {b0.x, b0.y, b0.z, b0.w, b1.x, b1.y, b1.z, b1.w};
    float sc[8], s4[8];
    #pragma unroll
    for (int i = 0; i < 8; i++) {
        float s = 1.0f / (1.0f + expf(-lv[i]));
        sc[i] = s;
        s4[i] = s + bb[i];
    }

    float m1 = -CUDART_INF_F, m2 = -CUDART_INF_F, m3 = -CUDART_INF_F;
    #pragma unroll
    for (int i = 0; i < 8; i++) {
        float v = s4[i];
        if (v > m1)      { m3 = m2; m2 = m1; m1 = v; }
        else if (v > m2) { m3 = m2; m2 = v; }
        else if (v > m3) { m3 = v; }
    }
    #pragma unroll
    for (int d = 1; d <= 2; d <<= 1) {
        float o1 = __shfl_xor_sync(FULL, m1, d);
        float o2 = __shfl_xor_sync(FULL, m2, d);
        float o3 = __shfl_xor_sync(FULL, m3, d);
        float mn1 = fminf(m1, o1);
        float mx2 = fmaxf(m2, o2);
        float n1 = fmaxf(m1, o1);
        float n2 = fmaxf(mn1, mx2);
        float n3 = fmaxf(fminf(mn1, mx2), fmaxf(m3, o3));
        m1 = n1; m2 = n2; m3 = n3;
    }
    const float gs  = m1 + m2;
    const float m23 = m2 - m3;
    const int   g   = lane >> 2;

    int rank = 0;
    #pragma unroll
    for (int j = 0; j < 8; j++) {
        float gj = __shfl_sync(FULL, gs, j * 4);
        rank += (gj > gs) || (gj == gs && j < g);
    }
    const int selg = (rank < 4);
    if (!selg) {
        #pragma unroll
        for (int i = 0; i < 8; i++) s4[i] = 0.0f;   // reference: score * mask
    }

    float flagmin = CUDART_INF_F;
    if (do_flag) {
        float vsel = selg ? gs : CUDART_INF_F;
        float vuns = selg ? -CUDART_INF_F : gs;
        float mm   = m23;
        #pragma unroll
        for (int d = 16; d; d >>= 1) {
            vsel = fminf(vsel, __shfl_xor_sync(FULL, vsel, d));
            vuns = fmaxf(vuns, __shfl_xor_sync(FULL, vuns, d));
            mm   = fminf(mm,   __shfl_xor_sync(FULL, mm,   d));
        }
        flagmin = fminf(vsel - vuns, mm);
    }

    float wsum = 0.0f, my_w = 0.0f, prevv = 0.0f;
    int   my_ix = 0;
    #pragma unroll
    for (int t = 0; t < 8; t++) {
        float bv = s4[0]; int bp = 0;
        #pragma unroll
        for (int i = 1; i < 8; i++)
            if (s4[i] > bv) { bv = s4[i]; bp = i; }
        float v  = bv;
        int   ix = lane * 8 + bp;
        #pragma unroll
        for (int d = 16; d; d >>= 1) {
            float ov = __shfl_xor_sync(FULL, v, d);
            int   oi = __shfl_xor_sync(FULL, ix, d);
            if (ov > v || (ov == v && oi < ix)) { v = ov; ix = oi; }
        }
        if (t > 0) flagmin = fminf(flagmin, prevv - v);
        prevv = v;
        const int opos  = ix & 7;
        const int olane = ix >> 3;
        #pragma unroll
        for (int i = 0; i < 8; i++)
            if (lane == olane && i == opos) s4[i] = -CUDART_INF_F;
        float cand = sc[0];
        #pragma unroll
        for (int i = 1; i < 8; i++)
            if (i == opos) cand = sc[i];
        float w = __shfl_sync(FULL, cand, olane);
        wsum += w;
        if (lane == t) { my_w = w; my_ix = ix; }
    }

    if (do_flag) {
        float bv = s4[0];
        #pragma unroll
        for (int i = 1; i < 8; i++) bv = fmaxf(bv, s4[i]);
        #pragma unroll
        for (int d = 16; d; d >>= 1)
            bv = fmaxf(bv, __shfl_xor_sync(FULL, bv, d));
        flagmin = fminf(flagmin, prevv - bv);
        if (lane == 0 && flagmin < TAU) {
            int p = atomicAdd(&g_nflag, 1);
            g_flagged[p] = token;
        }
    }

    const float scale = 2.5f / (wsum + 1e-20f);
    if (lane < TOPK) {
        out[(size_t)token * TOPK + lane] = my_w * scale;
        if (write_idx)
            out[(size_t)TOKENS * TOPK + (size_t)token * TOPK + lane] = (float)my_ix;
    }
}

// ---------------------------------------------------------------------------
__global__ __launch_bounds__(256)
void routing_kernel(const float* __restrict__ bias, float* __restrict__ out,
                    int write_idx)
{
    const int lane  = threadIdx.x & 31;
    const int warp  = threadIdx.x >> 5;
    const int token = blockIdx.x * 8 + warp;
    route_one(g_logits + (size_t)token * NEXP, bias, out, write_idx, token,
              lane, 1);
}

// ---------------------------------------------------------------------------
__global__ __launch_bounds__(256)
void recompute_kernel(const float* __restrict__ A, const float* __restrict__ W,
                      const float* __restrict__ bias, float* __restrict__ out,
                      int write_idx)
{
    __shared__ __align__(16) float srow[HIDDEN];
    __shared__ __align__(16) float slog[NEXP];

    const int nf   = g_nflag;
    const int wid  = threadIdx.x >> 5;
    const int lane = threadIdx.x & 31;

    for (int it = blockIdx.x; it < nf; it += gridDim.x) {
        const int token = g_flagged[it];
        for (int i = threadIdx.x * 4; i < HIDDEN; i += 1024)
            *(float4*)(srow + i) = *(const float4*)(A + (size_t)token * HIDDEN + i);
        __syncthreads();

        for (int e = wid * 32; e < wid * 32 + 32; e++) {
            const float* wr = W + (size_t)e * HIDDEN;
            float a0 = 0.f, a1 = 0.f;
            for (int i = lane * 4; i < HIDDEN; i += 256) {
                float4 wv = *(const float4*)(wr + i);
                float4 av = *(const float4*)(srow + i);
                a0 += av.x * wv.x + av.y * wv.y + av.z * wv.z + av.w * wv.w;
                float4 wv2 = *(const float4*)(wr + i + 128);
                float4 av2 = *(const float4*)(srow + i + 128);
                a1 += av2.x * wv2.x + av2.y * wv2.y + av2.z * wv2.z + av2.w * wv2.w;
            }
            float acc = a0 + a1;
            #pragma unroll
            for (int d = 16; d; d >>= 1)
                acc += __shfl_xor_sync(0xffffffffu, acc, d);
            if (lane == 0) slog[e] = acc;
        }
        __syncthreads();

        if (wid == 0)
            route_one(slog, bias, out, write_idx, token, lane, 0);
        __syncthreads();
    }
}

// ---------------------------------------------------------------------------
extern "C" void kernel_launch(void* const* d_in, const int* in_sizes, int n_in,
                              void* d_out, int out_size)
{
    const float* hs   = (const float*)d_in[0];  // [16384, 7168]
    const float* w    = (const float*)d_in[1];  // [256, 7168]
    const float* bias = (const float*)d_in[2];  // [256]
    float* out = (float*)d_out;

    cudaFuncSetAttribute(gemm_ffma,
                         cudaFuncAttributeMaxDynamicSharedMemorySize,
                         SMEM_TOTAL);

    convert_b_kernel<<<NCH, 256>>>(w);
    gemm_ffma<<<TOKENS / 128, 256, SMEM_TOTAL>>>(hs);

    const int write_idx = (out_size >= TOKENS * TOPK * 2) ? 1 : 0;
    routing_kernel<<<TOKENS / 8, 256>>>(bias, out, write_idx);
    recompute_kernel<<<128, 256>>>(hs, w, bias, out, write_idx);
}

// round 9
// speedup vs baseline: 1.0786x; 1.0786x over previous
#include <cuda_runtime.h>
#include <math_constants.h>
#include <math.h>
#include <cstdint>

#define TOKENS 16384
#define HIDDEN 7168
#define NEXP   256
#define TOPK   8
#define BK     16
#define NCH    (HIDDEN / BK)   // 448
#define TAU    1e-4f

// SMEM per stage: A [16][128] f32 = 8KB | B [16][256] f32 = 16KB
#define ST_BYTES 24576
#define OFF_A    0
#define OFF_B    8192
// allocation: reused as 128x256 f32 logits buffer (128KB) after main loop
#define SMEM_TOTAL 131072

__device__ float g_Bt[(size_t)NEXP * HIDDEN];    // chunk-blocked [ch][k][n]
__device__ int   g_nflag;
__device__ int   g_flagged[TOKENS];

#define CPA16(dst, src) \
    asm volatile("cp.async.cg.shared.global [%0], [%1], 16;" \
                 :: "r"(dst), "l"(src) : "memory")

#define LDS128F(v, addr) \
    asm volatile("ld.shared.v4.f32 {%0,%1,%2,%3}, [%4];" \
                 : "=f"((v).x), "=f"((v).y), "=f"((v).z), "=f"((v).w) : "r"(addr))

// ---------------------------------------------------------------------------
// Kernel 0: transpose W [n][k] -> g_Bt [chunk][k][n] (SMEM-image layout).
// (validated in R8: rel_err 2.5e-7 end-to-end)
// ---------------------------------------------------------------------------
__global__ __launch_bounds__(256)
void convert_b_kernel(const float* __restrict__ W) {
    if (blockIdx.x == 0 && threadIdx.x == 0) g_nflag = 0;   // per-launch reset

    const int ch = blockIdx.x;
    const int n  = threadIdx.x;
    const float* src = W + (size_t)n * HIDDEN + ch * BK;
    float* dst = g_Bt + (size_t)ch * (BK * NEXP);
    #pragma unroll
    for (int j = 0; j < 4; j++) {
        float4 v = *(const float4*)(src + 4 * j);
        dst[(4 * j + 0) * NEXP + n] = v.x;
        dst[(4 * j + 1) * NEXP + n] = v.y;
        dst[(4 * j + 2) * NEXP + n] = v.z;
        dst[(4 * j + 3) * NEXP + n] = v.w;
    }
}

// ---------------------------------------------------------------------------
// route_one: reference-exact routing for one token (validated R4-R8).
// ---------------------------------------------------------------------------
__device__ __forceinline__ void route_one(const float* __restrict__ row,
                                          const float* __restrict__ bias,
                                          float* __restrict__ out,
                                          int write_idx, int token, int lane,
                                          int do_flag)
{
    const unsigned FULL = 0xffffffffu;

    float4 l0 = *(const float4*)(row + lane * 8);
    float4 l1 = *(const float4*)(row + lane * 8 + 4);
    float4 b0 = *(const float4*)(bias + lane * 8);
    float4 b1 = *(const float4*)(bias + lane * 8 + 4);

    float lv[8] = {l0.x, l0.y, l0.z, l0.w, l1.x, l1.y, l1.z, l1.w};
    float bb[8] = {b0.x, b0.y, b0.z, b0.w, b1.x, b1.y, b1.z, b1.w};
    float sc[8], s4[8];
    #pragma unroll
    for (int i = 0; i < 8; i++) {
        float s = 1.0f / (1.0f + expf(-lv[i]));
        sc[i] = s;
        s4[i] = s + bb[i];
    }

    float m1 = -CUDART_INF_F, m2 = -CUDART_INF_F, m3 = -CUDART_INF_F;
    #pragma unroll
    for (int i = 0; i < 8; i++) {
        float v = s4[i];
        if (v > m1)      { m3 = m2; m2 = m1; m1 = v; }
        else if (v > m2) { m3 = m2; m2 = v; }
        else if (v > m3) { m3 = v; }
    }
    #pragma unroll
    for (int d = 1; d <= 2; d <<= 1) {
        float o1 = __shfl_xor_sync(FULL, m1, d);
        float o2 = __shfl_xor_sync(FULL, m2, d);
        float o3 = __shfl_xor_sync(FULL, m3, d);
        float mn1 = fminf(m1, o1);
        float mx2 = fmaxf(m2, o2);
        float n1 = fmaxf(m1, o1);
        float n2 = fmaxf(mn1, mx2);
        float n3 = fmaxf(fminf(mn1, mx2), fmaxf(m3, o3));
        m1 = n1; m2 = n2; m3 = n3;
    }
    const float gs  = m1 + m2;
    const float m23 = m2 - m3;
    const int   g   = lane >> 2;

    int rank = 0;
    #pragma unroll
    for (int j = 0; j < 8; j++) {
        float gj = __shfl_sync(FULL, gs, j * 4);
        rank += (gj > gs) || (gj == gs && j < g);
    }
    const int selg = (rank < 4);
    if (!selg) {
        #pragma unroll
        for (int i = 0; i < 8; i++) s4[i] = 0.0f;   // reference: score * mask
    }

    float flagmin = CUDART_INF_F;
    if (do_flag) {
        float vsel = selg ? gs : CUDART_INF_F;
        float vuns = selg ? -CUDART_INF_F : gs;
        float mm   = m23;
        #pragma unroll
        for (int d = 16; d; d >>= 1) {
            vsel = fminf(vsel, __shfl_xor_sync(FULL, vsel, d));
            vuns = fmaxf(vuns, __shfl_xor_sync(FULL, vuns, d));
            mm   = fminf(mm,   __shfl_xor_sync(FULL, mm,   d));
        }
        flagmin = fminf(vsel - vuns, mm);
    }

    float wsum = 0.0f, my_w = 0.0f, prevv = 0.0f;
    int   my_ix = 0;
    #pragma unroll
    for (int t = 0; t < 8; t++) {
        float bv = s4[0]; int bp = 0;
        #pragma unroll
        for (int i = 1; i < 8; i++)
            if (s4[i] > bv) { bv = s4[i]; bp = i; }
        float v  = bv;
        int   ix = lane * 8 + bp;
        #pragma unroll
        for (int d = 16; d; d >>= 1) {
            float ov = __shfl_xor_sync(FULL, v, d);
            int   oi = __shfl_xor_sync(FULL, ix, d);
            if (ov > v || (ov == v && oi < ix)) { v = ov; ix = oi; }
        }
        if (t > 0) flagmin = fminf(flagmin, prevv - v);
        prevv = v;
        const int opos  = ix & 7;
        const int olane = ix >> 3;
        #pragma unroll
        for (int i = 0; i < 8; i++)
            if (lane == olane && i == opos) s4[i] = -CUDART_INF_F;
        float cand = sc[0];
        #pragma unroll
        for (int i = 1; i < 8; i++)
            if (i == opos) cand = sc[i];
        float w = __shfl_sync(FULL, cand, olane);
        wsum += w;
        if (lane == t) { my_w = w; my_ix = ix; }
    }

    if (do_flag) {
        float bv = s4[0];
        #pragma unroll
        for (int i = 1; i < 8; i++) bv = fmaxf(bv, s4[i]);
        #pragma unroll
        for (int d = 16; d; d >>= 1)
            bv = fmaxf(bv, __shfl_xor_sync(FULL, bv, d));
        flagmin = fminf(flagmin, prevv - bv);
        if (lane == 0 && flagmin < TAU) {
            int p = atomicAdd(&g_nflag, 1);
            g_flagged[p] = token;
        }
    }

    const float scale = 2.5f / (wsum + 1e-20f);
    if (lane < TOPK) {
        out[(size_t)token * TOPK + lane] = my_w * scale;
        if (write_idx)
            out[(size_t)TOKENS * TOPK + (size_t)token * TOPK + lane] = (float)my_ix;
    }
}

// ---------------------------------------------------------------------------
// Kernel 1: fused fp32 SGEMM + routing. One 512-thread CTA per SM.
// CTA = 128 tokens x 256 experts (grid 128), per-thread tile 8x8
// (R1's proven mapping: broadcast a-loads, conflict-free b-loads),
// BK=16 double-buffered, cp.async B from g_Bt, LDG+STS A.
// Epilogue: logits -> SMEM, route in-CTA (no logits DRAM round-trip).
// ---------------------------------------------------------------------------
__global__ __launch_bounds__(512, 1)
void gemm_fused(const float* __restrict__ A, const float* __restrict__ bias,
                float* __restrict__ out, int write_idx)
{
    extern __shared__ char smem[];
    uint32_t sb;
    asm("{ .reg .u64 t; cvta.to.shared.u64 t, %1; cvt.u32.u64 %0, t; }"
        : "=r"(sb) : "l"((void*)smem));

    const int tid = threadIdx.x;
    const int tx  = tid & 31;           // N: cols tx*4 and tx*4+128
    const int ty  = tid >> 5;           // M: rows ty*4 and ty*4+64
    const int bm  = blockIdx.x * 128;

    // A loader: 4 threads/row, 4 consecutive k each
    const int arow  = tid >> 2;
    const int apart = tid & 3;
    const float* Agp = A + (size_t)(bm + arow) * HIDDEN + apart * 4;

    float cc[8][8];
    #pragma unroll
    for (int i = 0; i < 8; i++)
        #pragma unroll
        for (int j = 0; j < 8; j++) cc[i][j] = 0.0f;

#define LOAD_B_ASYNC(nc, st) do {                                              \
        const float* __s = g_Bt + (size_t)(nc) * (BK * NEXP) + tid * 8;        \
        uint32_t __d = sb + (st) * ST_BYTES + OFF_B + tid * 32;                \
        CPA16(__d, __s);                                                       \
        CPA16(__d + 16, __s + 4);                                              \
        asm volatile("cp.async.commit_group;" ::: "memory");                   \
    } while (0)

#define STORE_A(st, v) do {                                                    \
        const uint32_t __ab = sb + (st) * ST_BYTES + OFF_A + arow * 4;         \
        asm volatile("st.shared.f32 [%0], %1;" :: "r"(__ab + (apart*4+0)*512), \
                     "f"((v).x) : "memory");                                   \
        asm volatile("st.shared.f32 [%0], %1;" :: "r"(__ab + (apart*4+1)*512), \
                     "f"((v).y) : "memory");                                   \
        asm volatile("st.shared.f32 [%0], %1;" :: "r"(__ab + (apart*4+2)*512), \
                     "f"((v).z) : "memory");                                   \
        asm volatile("st.shared.f32 [%0], %1;" :: "r"(__ab + (apart*4+3)*512), \
                     "f"((v).w) : "memory");                                   \
    } while (0)

    // ---- prologue: stage 0 ----
    {
        LOAD_B_ASYNC(0, 0);
        float4 v = __ldg((const float4*)Agp);
        STORE_A(0, v);
        asm volatile("cp.async.wait_group 0;" ::: "memory");
        __syncthreads();
    }

    // ---- main loop over 448 chunks of K=16 ----
    for (int c = 0; c < NCH; c++) {
        const int s   = c & 1;
        const bool np = (c + 1 < NCH);
        float4 av;
        if (np) {
            LOAD_B_ASYNC(c + 1, s ^ 1);
            av = __ldg((const float4*)(Agp + (size_t)(c + 1) * BK));
        }

        const uint32_t abase = sb + s * ST_BYTES + OFF_A + ty * 16;
        const uint32_t bbase = sb + s * ST_BYTES + OFF_B + tx * 16;

        #pragma unroll 8
        for (int k = 0; k < BK; k++) {
            float4 a0, a1, b0, b1;
            LDS128F(a0, abase + k * 512);          // rows ty*4..+3
            LDS128F(a1, abase + k * 512 + 256);    // rows ty*4+64..
            LDS128F(b0, bbase + k * 1024);         // cols tx*4..+3
            LDS128F(b1, bbase + k * 1024 + 512);   // cols tx*4+128..
            float ar[8] = {a0.x, a0.y, a0.z, a0.w, a1.x, a1.y, a1.z, a1.w};
            float br[8] = {b0.x, b0.y, b0.z, b0.w, b1.x, b1.y, b1.z, b1.w};
            #pragma unroll
            for (int i = 0; i < 8; i++)
                #pragma unroll
                for (int j = 0; j < 8; j++)
                    cc[i][j] += ar[i] * br[j];
        }

        if (np) {
            STORE_A(s ^ 1, av);
            asm volatile("cp.async.wait_group 0;" ::: "memory");
        }
        __syncthreads();
    }

    // ---- epilogue: logits -> SMEM (128 x 256 f32 = 128KB) ----
    float* slog = (float*)smem;
    #pragma unroll
    for (int i = 0; i < 4; i++) {
        const int r0 = ty * 4 + i;
        const int r1 = r0 + 64;
        *(float4*)(slog + r0 * NEXP + tx * 4) =
            make_float4(cc[i][0], cc[i][1], cc[i][2], cc[i][3]);
        *(float4*)(slog + r0 * NEXP + tx * 4 + 128) =
            make_float4(cc[i][4], cc[i][5], cc[i][6], cc[i][7]);
        *(float4*)(slog + r1 * NEXP + tx * 4) =
            make_float4(cc[i+4][0], cc[i+4][1], cc[i+4][2], cc[i+4][3]);
        *(float4*)(slog + r1 * NEXP + tx * 4 + 128) =
            make_float4(cc[i+4][4], cc[i+4][5], cc[i+4][6], cc[i+4][7]);
    }
    __syncthreads();

    // ---- fused routing: warp ty routes tokens ty*8 .. ty*8+7 ----
    #pragma unroll 1
    for (int t = 0; t < 8; t++) {
        const int lt = ty * 8 + t;
        route_one(slog + (size_t)lt * NEXP, bias, out, write_idx, bm + lt,
                  tx, 1);
    }
}

// ---------------------------------------------------------------------------
// Kernel 2: fp32 recompute + re-route for flagged tokens (validated R4-R8).
// ---------------------------------------------------------------------------
__global__ __launch_bounds__(256)
void recompute_kernel(const float* __restrict__ A, const float* __restrict__ W,
                      const float* __restrict__ bias, float* __restrict__ out,
                      int write_idx)
{
    __shared__ __align__(16) float srow[HIDDEN];
    __shared__ __align__(16) float slog[NEXP];

    const int nf   = g_nflag;
    const int wid  = threadIdx.x >> 5;
    const int lane = threadIdx.x & 31;

    for (int it = blockIdx.x; it < nf; it += gridDim.x) {
        const int token = g_flagged[it];
        for (int i = threadIdx.x * 4; i < HIDDEN; i += 1024)
            *(float4*)(srow + i) = *(const float4*)(A + (size_t)token * HIDDEN + i);
        __syncthreads();

        for (int e = wid * 32; e < wid * 32 + 32; e++) {
            const float* wr = W + (size_t)e * HIDDEN;
            float a0 = 0.f, a1 = 0.f;
            for (int i = lane * 4; i < HIDDEN; i += 256) {
                float4 wv = *(const float4*)(wr + i);
                float4 av = *(const float4*)(srow + i);
                a0 += av.x * wv.x + av.y * wv.y + av.z * wv.z + av.w * wv.w;
                float4 wv2 = *(const float4*)(wr + i + 128);
                float4 av2 = *(const float4*)(srow + i + 128);
                a1 += av2.x * wv2.x + av2.y * wv2.y + av2.z * wv2.z + av2.w * wv2.w;
            }
            float acc = a0 + a1;
            #pragma unroll
            for (int d = 16; d; d >>= 1)
                acc += __shfl_xor_sync(0xffffffffu, acc, d);
            if (lane == 0) slog[e] = acc;
        }
        __syncthreads();

        if (wid == 0)
            route_one(slog, bias, out, write_idx, token, lane, 0);
        __syncthreads();
    }
}

// ---------------------------------------------------------------------------
extern "C" void kernel_launch(void* const* d_in, const int* in_sizes, int n_in,
                              void* d_out, int out_size)
{
    const float* hs   = (const float*)d_in[0];  // [16384, 7168]
    const float* w    = (const float*)d_in[1];  // [256, 7168]
    const float* bias = (const float*)d_in[2];  // [256]
    float* out = (float*)d_out;

    cudaFuncSetAttribute(gemm_fused,
                         cudaFuncAttributeMaxDynamicSharedMemorySize,
                         SMEM_TOTAL);

    const int write_idx = (out_size >= TOKENS * TOPK * 2) ? 1 : 0;

    convert_b_kernel<<<NCH, 256>>>(w);
    gemm_fused<<<TOKENS / 128, 512, SMEM_TOTAL>>>(hs, bias, out, write_idx);
    recompute_kernel<<<128, 256>>>(hs, w, bias, out, write_idx);
}